// round 16
// baseline (speedup 1.0000x reference)
#include <cuda_runtime.h>
#include <cuda_fp16.h>
#include <cstdint>
#include <math.h>

#define B_   128
#define C_   272
#define T_   1024
#define D_   270
#define KK_  1024
#define NCHUNK 16
#define NMT  18       // 288/16 d-fragment tiles
#define NKS  17       // 272/16 k-steps (covers C_ exactly)

// Scratch (device globals; allocation-free contract). Zero-initialized.
__device__ float g_cosP[KK_ * C_];
__device__ float g_sinP[KK_ * C_];
__device__ float g_Apart[NCHUNK * D_ * C_];
__device__ uint4  g_Wfrag[NMT * NKS * 32];            // W in A-fragment layout (fp16)
__device__ uint4  g_Xfrag[(size_t)B_ * NKS * 64 * 32]; // X in B-fragment layout (fp16), 71MB

__device__ __forceinline__ uint32_t smem_u32(const void* p) {
    uint32_t a;
    asm("{ .reg .u64 t; cvta.to.shared.u64 t, %1; cvt.u32.u64 %0, t; }" : "=r"(a) : "l"(p));
    return a;
}

#define LDSM_X4_T(r, a)                                                      \
    asm volatile("ldmatrix.sync.aligned.m8n8.x4.trans.shared.b16 {%0,%1,%2,%3}, [%4];" \
        : "=r"((r)[0]), "=r"((r)[1]), "=r"((r)[2]), "=r"((r)[3]) : "r"(a))

#define MMA16816F(d, a, b0v, b1v)                                            \
    asm volatile("mma.sync.aligned.m16n8k16.row.col.f32.f16.f16.f32 "        \
        "{%0,%1,%2,%3}, {%4,%5,%6,%7}, {%8,%9}, {%0,%1,%2,%3};"              \
        : "+f"((d)[0]), "+f"((d)[1]), "+f"((d)[2]), "+f"((d)[3])             \
        : "r"((a)[0]), "r"((a)[1]), "r"((a)[2]), "r"((a)[3]),                \
          "r"(b0v), "r"(b1v))

// ---------------------------------------------------------------------------
// Stage 1: trig table (reference-exact f32 phase; sincosf 2-ulp).
// ---------------------------------------------------------------------------
__global__ void trig_kernel(const float* __restrict__ loc) {
    int kl = blockIdx.x;
    int c  = threadIdx.x;
    float x = loc[2 * c];
    float y = loc[2 * c + 1];
    float kf = (float)(kl >> 5);
    float lf = (float)(kl & 31);
    float s = __fadd_rn(__fmul_rn(kf, x), __fmul_rn(lf, y));
    float p = __fmul_rn(6.28318530717958647692f, s);
    float sd, cd;
    sincosf(p, &sd, &cd);
    g_cosP[kl * C_ + c] = cd;
    g_sinP[kl * C_ + c] = sd;
}

// ---------------------------------------------------------------------------
// Stage 2: A[d,c] partials (deterministic, per-kl-chunk buffers).
// ---------------------------------------------------------------------------
__global__ void a_kernel(const float* __restrict__ zre, const float* __restrict__ zim) {
    __shared__ float s_zre[16][64];
    __shared__ float s_zim[16][64];
    int d0  = blockIdx.x * 16;
    int kl0 = blockIdx.y * 64;
    int tid = threadIdx.x;

    for (int i = tid; i < 16 * 64; i += 272) {
        int dd = i >> 6, j = i & 63;
        int d = d0 + dd;
        float vr = 0.f, vi = 0.f;
        if (d < D_) {
            vr = zre[d * KK_ + kl0 + j];
            vi = zim[d * KK_ + kl0 + j];
        }
        s_zre[dd][j] = vr;
        s_zim[dd][j] = vi;
    }
    __syncthreads();

    int c = tid;
    float acc[16];
#pragma unroll
    for (int i = 0; i < 16; i++) acc[i] = 0.f;

    for (int j = 0; j < 64; j++) {
        float cv = g_cosP[(kl0 + j) * C_ + c];
        float sv = g_sinP[(kl0 + j) * C_ + c];
#pragma unroll
        for (int i = 0; i < 16; i++)
            acc[i] = fmaf(s_zre[i][j], cv, fmaf(s_zim[i][j], sv, acc[i]));
    }

#pragma unroll
    for (int i = 0; i < 16; i++) {
        int d = d0 + i;
        if (d < D_)
            g_Apart[(blockIdx.y * D_ + d) * C_ + c] = acc[i];
    }
}

// ---------------------------------------------------------------------------
// Stage 3: softmax over c per row d; scatter fp16 weights directly into the
// m16n8k16 A-fragment layout. Padding slots stay zero-init.
// ---------------------------------------------------------------------------
__device__ __forceinline__ void scatter_w(int d, int c, float w) {
    int mt = d >> 4, ks = c >> 4, dr = d & 15, cr = c & 15;
    int lane = (dr & 7) * 4 + ((cr & 7) >> 1);
    int reg  = ((dr >> 3) & 1) + ((cr >> 3) & 1) * 2;
    __half* wf = (__half*)g_Wfrag;
    wf[(size_t)((mt * NKS + ks) * 32 + lane) * 8 + reg * 2 + (cr & 1)] = __float2half_rn(w);
}

__global__ void softmax_kernel() {
    int d   = blockIdx.x;
    int tid = threadIdx.x;   // 256
    __shared__ float s_red[256];

    float v0 = 0.f;
#pragma unroll
    for (int h = 0; h < NCHUNK; h++) v0 += g_Apart[(h * D_ + d) * C_ + tid];

    float v1 = __int_as_float(0xff800000);
    if (tid < C_ - 256) {
        v1 = 0.f;
#pragma unroll
        for (int h = 0; h < NCHUNK; h++) v1 += g_Apart[(h * D_ + d) * C_ + 256 + tid];
    }

    s_red[tid] = fmaxf(v0, v1);
    __syncthreads();
    for (int s = 128; s > 0; s >>= 1) {
        if (tid < s) s_red[tid] = fmaxf(s_red[tid], s_red[tid + s]);
        __syncthreads();
    }
    float mx = s_red[0];
    __syncthreads();

    float e0 = expf(v0 - mx);
    float e1 = (tid < C_ - 256) ? expf(v1 - mx) : 0.f;
    s_red[tid] = e0 + e1;
    __syncthreads();
    for (int s = 128; s > 0; s >>= 1) {
        if (tid < s) s_red[tid] += s_red[tid + s];
        __syncthreads();
    }
    float inv = 1.f / s_red[0];

    scatter_w(d, tid, e0 * inv);
    if (tid < C_ - 256) scatter_w(d, 256 + tid, e1 * inv);
}

// ---------------------------------------------------------------------------
// Stage 3c: xcvt — convert X fp32 -> fp16 B-fragments (m16n8k16 col-major).
// Block = (ks, b), 256 threads. Load 16c x 1024t tile, cvt to fp16 in smem
// ([c][t], the layout the proven ldmatrix.trans path expects), then each
// warp LDSM.x4.trans + STG.128 fragments.
// g_Xfrag[((b*NKS + ks)*64 + ttp)*32 + lane] = {nt_even.b0,b1, nt_odd.b0,b1}
// where ttp = t/16.
// ---------------------------------------------------------------------------
#define XS 1032
__global__ __launch_bounds__(256) void xcvt_kernel(const float* __restrict__ X) {
    __shared__ __align__(16) __half sx[16][XS];
    int ks = blockIdx.x, b = blockIdx.y;
    int tid = threadIdx.x, wid = tid >> 5, lane = tid & 31;
    const float* Xp = X + ((size_t)b * C_ + ks * 16) * T_;

#pragma unroll
    for (int k = 0; k < 16; k++) {
        int f = tid + k * 256;
        int r = f >> 8, col = (f & 255) * 4;
        float4 v = *(const float4*)(Xp + (size_t)r * T_ + col);
        __half2 p0 = __floats2half2_rn(v.x, v.y);
        __half2 p1 = __floats2half2_rn(v.z, v.w);
        *(uint2*)&sx[r][col] = make_uint2(*(uint32_t*)&p0, *(uint32_t*)&p1);
    }
    __syncthreads();

    uint32_t sb  = smem_u32(sx);
    uint32_t laB = (uint32_t)((lane & 15) * (XS * 2) + (lane >> 4) * 16);
    uint4* dst = g_Xfrag + ((size_t)(b * NKS + ks) * 64 + wid * 8) * 32 + lane;

#pragma unroll
    for (int i = 0; i < 8; i++) {
        uint32_t addr = sb + laB + (uint32_t)((wid * 128 + i * 16) * 2);
        uint32_t r[4];
        LDSM_X4_T(r, addr);
        dst[(size_t)i * 32] = make_uint4(r[0], r[1], r[2], r[3]);
    }
}

// ---------------------------------------------------------------------------
// Stage 4: out[b,d,t] = sum_c w[d,c] * X[b,c,t] via mma.sync fp16.
// NO smem, NO syncs, NO ldmatrix: both operands arrive as ready fragments
// via LDG.128 from L2-hot precomputed buffers. 128-thread CTA: 96d x 64t,
// warps 2(d) x 2(t), warp tile 48d x 32t. Next-ks prefetch in regs.
// ---------------------------------------------------------------------------
__global__ __launch_bounds__(128, 5) void bdt_mma_kernel(float* __restrict__ out) {
    int tid  = threadIdx.x;
    int wid  = tid >> 5;
    int lane = tid & 31;
    int bx   = blockIdx.x;      // 0..2  (d)
    int by   = blockIdx.y;      // 0..15 (t)
    int b    = blockIdx.z;
    int wd   = wid >> 1;        // 0..1
    int wt   = wid & 1;         // 0..1
    int d0   = bx * 96;
    int t0   = by * 64;

    float acc[3][4][4];
#pragma unroll
    for (int m = 0; m < 3; m++)
#pragma unroll
        for (int n = 0; n < 4; n++)
#pragma unroll
            for (int k = 0; k < 4; k++) acc[m][n][k] = 0.f;

    const uint4* wf = g_Wfrag + (size_t)((bx * 6 + wd * 3) * NKS) * 32 + lane;
    const uint4* xf = g_Xfrag + ((size_t)(b * NKS) * 64 + by * 4 + wt * 2) * 32 + lane;

    uint4 af[3], bf[2];
#pragma unroll
    for (int mt = 0; mt < 3; mt++) af[mt] = __ldg(wf + (size_t)mt * NKS * 32);
    bf[0] = __ldg(xf);
    bf[1] = __ldg(xf + 32);

    for (int ks = 0; ks < NKS; ks++) {
        uint4 na[3], nb[2];
        if (ks + 1 < NKS) {
#pragma unroll
            for (int mt = 0; mt < 3; mt++)
                na[mt] = __ldg(wf + ((size_t)mt * NKS + ks + 1) * 32);
            nb[0] = __ldg(xf + (size_t)(ks + 1) * 64 * 32);
            nb[1] = __ldg(xf + (size_t)(ks + 1) * 64 * 32 + 32);
        }

#pragma unroll
        for (int mt = 0; mt < 3; mt++) {
            uint32_t ah[4] = {af[mt].x, af[mt].y, af[mt].z, af[mt].w};
            MMA16816F(acc[mt][0], ah, bf[0].x, bf[0].y);
            MMA16816F(acc[mt][1], ah, bf[0].z, bf[0].w);
            MMA16816F(acc[mt][2], ah, bf[1].x, bf[1].y);
            MMA16816F(acc[mt][3], ah, bf[1].z, bf[1].w);
        }

#pragma unroll
        for (int mt = 0; mt < 3; mt++) af[mt] = na[mt];
        bf[0] = nb[0];
        bf[1] = nb[1];
    }

    // ---- epilogue: fragment rows = d, cols = t ----
#pragma unroll
    for (int mt = 0; mt < 3; mt++) {
        int dr = d0 + wd * 48 + mt * 16 + (lane >> 2);
#pragma unroll
        for (int nt = 0; nt < 4; nt++) {
            int tt = t0 + wt * 32 + nt * 8 + (lane & 3) * 2;
            if (dr < D_)
                *(float2*)(out + ((size_t)b * D_ + dr) * T_ + tt) =
                    make_float2(acc[mt][nt][0], acc[mt][nt][1]);
            if (dr + 8 < D_)
                *(float2*)(out + ((size_t)b * D_ + dr + 8) * T_ + tt) =
                    make_float2(acc[mt][nt][2], acc[mt][nt][3]);
        }
    }
}

// ---------------------------------------------------------------------------
extern "C" void kernel_launch(void* const* d_in, const int* in_sizes, int n_in,
                              void* d_out, int out_size) {
    const float* X   = (const float*)d_in[0];
    const float* loc = (const float*)d_in[1];
    const float* zre = (const float*)d_in[2];
    const float* zim = (const float*)d_in[3];
    float* out = (float*)d_out;

    trig_kernel<<<KK_, C_>>>(loc);
    a_kernel<<<dim3(17, NCHUNK), 272>>>(zre, zim);
    softmax_kernel<<<D_, 256>>>();
    xcvt_kernel<<<dim3(NKS, B_), 256>>>(X);
    bdt_mma_kernel<<<dim3(3, 16, B_), 128>>>(out);
}

// round 17
// speedup vs baseline: 1.2256x; 1.2256x over previous
#include <cuda_runtime.h>
#include <cuda_fp16.h>
#include <cstdint>
#include <math.h>

#define B_   128
#define C_   272
#define T_   1024
#define D_   270
#define KK_  1024
#define NCHUNK 16
#define NMT  18       // 288/16 d-fragment tiles
#define NKS  17       // 272/16 k-steps (covers C_ exactly)

// Scratch (device globals; allocation-free contract). Zero-initialized.
__device__ float g_cosP[KK_ * C_];
__device__ float g_sinP[KK_ * C_];
__device__ float g_Apart[NCHUNK * D_ * C_];
__device__ uint4  g_Wfrag[NMT * NKS * 32];             // W in A-fragment layout (fp16)
__device__ uint4  g_Xfrag[(size_t)B_ * NKS * 64 * 32]; // X in B-fragment layout (fp16), 71MB

__device__ __forceinline__ uint32_t smem_u32(const void* p) {
    uint32_t a;
    asm("{ .reg .u64 t; cvta.to.shared.u64 t, %1; cvt.u32.u64 %0, t; }" : "=r"(a) : "l"(p));
    return a;
}

#define LDSM_X4_T(r, a)                                                      \
    asm volatile("ldmatrix.sync.aligned.m8n8.x4.trans.shared.b16 {%0,%1,%2,%3}, [%4];" \
        : "=r"((r)[0]), "=r"((r)[1]), "=r"((r)[2]), "=r"((r)[3]) : "r"(a))

#define MMA16816F(d, a, b0v, b1v)                                            \
    asm volatile("mma.sync.aligned.m16n8k16.row.col.f32.f16.f16.f32 "        \
        "{%0,%1,%2,%3}, {%4,%5,%6,%7}, {%8,%9}, {%0,%1,%2,%3};"              \
        : "+f"((d)[0]), "+f"((d)[1]), "+f"((d)[2]), "+f"((d)[3])             \
        : "r"((a)[0]), "r"((a)[1]), "r"((a)[2]), "r"((a)[3]),                \
          "r"(b0v), "r"(b1v))

// ---------------------------------------------------------------------------
// Stage 1: trig table (reference-exact f32 phase; sincosf 2-ulp).
// ---------------------------------------------------------------------------
__global__ void trig_kernel(const float* __restrict__ loc) {
    int kl = blockIdx.x;
    int c  = threadIdx.x;
    float x = loc[2 * c];
    float y = loc[2 * c + 1];
    float kf = (float)(kl >> 5);
    float lf = (float)(kl & 31);
    float s = __fadd_rn(__fmul_rn(kf, x), __fmul_rn(lf, y));
    float p = __fmul_rn(6.28318530717958647692f, s);
    float sd, cd;
    sincosf(p, &sd, &cd);
    g_cosP[kl * C_ + c] = cd;
    g_sinP[kl * C_ + c] = sd;
}

// ---------------------------------------------------------------------------
// Stage 2: A[d,c] partials (deterministic, per-kl-chunk buffers).
// ---------------------------------------------------------------------------
__global__ void a_kernel(const float* __restrict__ zre, const float* __restrict__ zim) {
    __shared__ float s_zre[16][64];
    __shared__ float s_zim[16][64];
    int d0  = blockIdx.x * 16;
    int kl0 = blockIdx.y * 64;
    int tid = threadIdx.x;

    for (int i = tid; i < 16 * 64; i += 272) {
        int dd = i >> 6, j = i & 63;
        int d = d0 + dd;
        float vr = 0.f, vi = 0.f;
        if (d < D_) {
            vr = zre[d * KK_ + kl0 + j];
            vi = zim[d * KK_ + kl0 + j];
        }
        s_zre[dd][j] = vr;
        s_zim[dd][j] = vi;
    }
    __syncthreads();

    int c = tid;
    float acc[16];
#pragma unroll
    for (int i = 0; i < 16; i++) acc[i] = 0.f;

    for (int j = 0; j < 64; j++) {
        float cv = g_cosP[(kl0 + j) * C_ + c];
        float sv = g_sinP[(kl0 + j) * C_ + c];
#pragma unroll
        for (int i = 0; i < 16; i++)
            acc[i] = fmaf(s_zre[i][j], cv, fmaf(s_zim[i][j], sv, acc[i]));
    }

#pragma unroll
    for (int i = 0; i < 16; i++) {
        int d = d0 + i;
        if (d < D_)
            g_Apart[(blockIdx.y * D_ + d) * C_ + c] = acc[i];
    }
}

// ---------------------------------------------------------------------------
// Stage 3: softmax over c per row d; scatter fp16 weights directly into the
// m16n8k16 A-fragment layout. Padding slots stay zero-init.
// ---------------------------------------------------------------------------
__device__ __forceinline__ void scatter_w(int d, int c, float w) {
    int mt = d >> 4, ks = c >> 4, dr = d & 15, cr = c & 15;
    int lane = (dr & 7) * 4 + ((cr & 7) >> 1);
    int reg  = ((dr >> 3) & 1) + ((cr >> 3) & 1) * 2;
    __half* wf = (__half*)g_Wfrag;
    wf[(size_t)((mt * NKS + ks) * 32 + lane) * 8 + reg * 2 + (cr & 1)] = __float2half_rn(w);
}

__global__ void softmax_kernel() {
    int d   = blockIdx.x;
    int tid = threadIdx.x;   // 256
    __shared__ float s_red[256];

    float v0 = 0.f;
#pragma unroll
    for (int h = 0; h < NCHUNK; h++) v0 += g_Apart[(h * D_ + d) * C_ + tid];

    float v1 = __int_as_float(0xff800000);
    if (tid < C_ - 256) {
        v1 = 0.f;
#pragma unroll
        for (int h = 0; h < NCHUNK; h++) v1 += g_Apart[(h * D_ + d) * C_ + 256 + tid];
    }

    s_red[tid] = fmaxf(v0, v1);
    __syncthreads();
    for (int s = 128; s > 0; s >>= 1) {
        if (tid < s) s_red[tid] = fmaxf(s_red[tid], s_red[tid + s]);
        __syncthreads();
    }
    float mx = s_red[0];
    __syncthreads();

    float e0 = expf(v0 - mx);
    float e1 = (tid < C_ - 256) ? expf(v1 - mx) : 0.f;
    s_red[tid] = e0 + e1;
    __syncthreads();
    for (int s = 128; s > 0; s >>= 1) {
        if (tid < s) s_red[tid] += s_red[tid + s];
        __syncthreads();
    }
    float inv = 1.f / s_red[0];

    scatter_w(d, tid, e0 * inv);
    if (tid < C_ - 256) scatter_w(d, 256 + tid, e1 * inv);
}

// ---------------------------------------------------------------------------
// Stage 3c: xcvt — convert X fp32 -> fp16 B-fragments (m16n8k16 col-major).
// ---------------------------------------------------------------------------
#define XS 1032
__global__ __launch_bounds__(256) void xcvt_kernel(const float* __restrict__ X) {
    __shared__ __align__(16) __half sx[16][XS];
    int ks = blockIdx.x, b = blockIdx.y;
    int tid = threadIdx.x, wid = tid >> 5, lane = tid & 31;
    const float* Xp = X + ((size_t)b * C_ + ks * 16) * T_;

#pragma unroll
    for (int k = 0; k < 16; k++) {
        int f = tid + k * 256;
        int r = f >> 8, col = (f & 255) * 4;
        float4 v = *(const float4*)(Xp + (size_t)r * T_ + col);
        __half2 p0 = __floats2half2_rn(v.x, v.y);
        __half2 p1 = __floats2half2_rn(v.z, v.w);
        *(uint2*)&sx[r][col] = make_uint2(*(uint32_t*)&p0, *(uint32_t*)&p1);
    }
    __syncthreads();

    uint32_t sb  = smem_u32(sx);
    uint32_t laB = (uint32_t)((lane & 15) * (XS * 2) + (lane >> 4) * 16);
    uint4* dst = g_Xfrag + ((size_t)(b * NKS + ks) * 64 + wid * 8) * 32 + lane;

#pragma unroll
    for (int i = 0; i < 8; i++) {
        uint32_t addr = sb + laB + (uint32_t)((wid * 128 + i * 16) * 2);
        uint32_t r[4];
        LDSM_X4_T(r, addr);
        dst[(size_t)i * 32] = make_uint4(r[0], r[1], r[2], r[3]);
    }
}

// ---------------------------------------------------------------------------
// Stage 4: out[b,d,t] = sum_c w[d,c] * X[b,c,t] via mma.sync fp16.
// No smem / syncs / ldmatrix: ready fragments via LDG.128.
// A (W, L1-hot) prefetched 1 ks ahead; B (X, L2-latency) 2 ks ahead via
// 3-slot rotation. Fully unrolled ks loop -> constant slot indices.
// 128-thread CTA: 96d x 64t, warps 2(d) x 2(t), warp tile 48d x 32t.
// ---------------------------------------------------------------------------
__global__ __launch_bounds__(128, 4) void bdt_mma_kernel(float* __restrict__ out) {
    int tid  = threadIdx.x;
    int wid  = tid >> 5;
    int lane = tid & 31;
    int bx   = blockIdx.x;      // 0..2  (d)
    int by   = blockIdx.y;      // 0..15 (t)
    int b    = blockIdx.z;
    int wd   = wid >> 1;        // 0..1
    int wt   = wid & 1;         // 0..1
    int d0   = bx * 96;
    int t0   = by * 64;

    float acc[3][4][4];
#pragma unroll
    for (int m = 0; m < 3; m++)
#pragma unroll
        for (int n = 0; n < 4; n++)
#pragma unroll
            for (int k = 0; k < 4; k++) acc[m][n][k] = 0.f;

    const uint4* wf = g_Wfrag + (size_t)((bx * 6 + wd * 3) * NKS) * 32 + lane;
    const uint4* xf = g_Xfrag + ((size_t)(b * NKS) * 64 + by * 4 + wt * 2) * 32 + lane;

    uint4 af[2][3];     // A slots: ks & 1
    uint4 bf[3][2];     // B slots: ks % 3, loaded 2 ahead

    // prologue: A for ks0; B for ks0, ks1
#pragma unroll
    for (int mt = 0; mt < 3; mt++) af[0][mt] = __ldg(wf + (size_t)mt * NKS * 32);
    bf[0][0] = __ldg(xf);
    bf[0][1] = __ldg(xf + 32);
    bf[1][0] = __ldg(xf + (size_t)64 * 32);
    bf[1][1] = __ldg(xf + (size_t)64 * 32 + 32);

#pragma unroll
    for (int ks = 0; ks < NKS; ks++) {
        const int ca = ks & 1;
        const int cb = ks % 3;

        // prefetch A for ks+1 (L1-hot), B for ks+2 (L2 latency, 2-deep)
        if (ks + 1 < NKS) {
#pragma unroll
            for (int mt = 0; mt < 3; mt++)
                af[ca ^ 1][mt] = __ldg(wf + ((size_t)mt * NKS + ks + 1) * 32);
        }
        if (ks + 2 < NKS) {
            const int nb = (ks + 2) % 3;
            bf[nb][0] = __ldg(xf + (size_t)(ks + 2) * 64 * 32);
            bf[nb][1] = __ldg(xf + (size_t)(ks + 2) * 64 * 32 + 32);
        }

#pragma unroll
        for (int mt = 0; mt < 3; mt++) {
            uint32_t ah[4] = {af[ca][mt].x, af[ca][mt].y, af[ca][mt].z, af[ca][mt].w};
            MMA16816F(acc[mt][0], ah, bf[cb][0].x, bf[cb][0].y);
            MMA16816F(acc[mt][1], ah, bf[cb][0].z, bf[cb][0].w);
            MMA16816F(acc[mt][2], ah, bf[cb][1].x, bf[cb][1].y);
            MMA16816F(acc[mt][3], ah, bf[cb][1].z, bf[cb][1].w);
        }
    }

    // ---- epilogue: fragment rows = d, cols = t ----
#pragma unroll
    for (int mt = 0; mt < 3; mt++) {
        int dr = d0 + wd * 48 + mt * 16 + (lane >> 2);
#pragma unroll
        for (int nt = 0; nt < 4; nt++) {
            int tt = t0 + wt * 32 + nt * 8 + (lane & 3) * 2;
            if (dr < D_)
                *(float2*)(out + ((size_t)b * D_ + dr) * T_ + tt) =
                    make_float2(acc[mt][nt][0], acc[mt][nt][1]);
            if (dr + 8 < D_)
                *(float2*)(out + ((size_t)b * D_ + dr + 8) * T_ + tt) =
                    make_float2(acc[mt][nt][2], acc[mt][nt][3]);
        }
    }
}

// ---------------------------------------------------------------------------
extern "C" void kernel_launch(void* const* d_in, const int* in_sizes, int n_in,
                              void* d_out, int out_size) {
    const float* X   = (const float*)d_in[0];
    const float* loc = (const float*)d_in[1];
    const float* zre = (const float*)d_in[2];
    const float* zim = (const float*)d_in[3];
    float* out = (float*)d_out;

    trig_kernel<<<KK_, C_>>>(loc);
    a_kernel<<<dim3(17, NCHUNK), 272>>>(zre, zim);
    softmax_kernel<<<D_, 256>>>();
    xcvt_kernel<<<dim3(NKS, B_), 256>>>(X);
    bdt_mma_kernel<<<dim3(3, 16, B_), 128>>>(out);
}